// round 8
// baseline (speedup 1.0000x reference)
#include <cuda_runtime.h>
#include <cuda_bf16.h>
#include <cstdint>

#define NCLASS 1024
#define DIM    256
#define KSZ    8
#define NSAMP  8192
#define TTILE  16         // 16x16 tiles of 64
#define TS     64         // tile size
#define NPAIR  136        // upper-triangle tile count (16*17/2)
#define NBLK   16         // class blocks of 64

// ---------------- scratch (no allocations allowed) ----------------
__device__ __align__(16) __nv_bfloat16 g_cbf[NCLASS * DIM];
__device__ float g_sq[NCLASS];
__device__ float g_pc[NCLASS];       // per-class dist_pc partial
__device__ float g_ph[NPAIR];        // per-tile hinge partial
__device__ unsigned g_rdy[NBLK];     // per-block class-completion counters (self-resetting)
__device__ unsigned g_cnt = 0;       // finalize counter (self-resetting)

__device__ __forceinline__ uint32_t smem_u32(const void* p) {
    uint32_t a;
    asm("{ .reg .u64 t; cvta.to.shared.u64 t, %1; cvt.u32.u64 %0, t; }" : "=r"(a) : "l"(p));
    return a;
}
__device__ __forceinline__ void ldm_x4(uint32_t* r, uint32_t addr) {
    asm volatile("ldmatrix.sync.aligned.m8n8.x4.shared.b16 {%0,%1,%2,%3}, [%4];"
                 : "=r"(r[0]), "=r"(r[1]), "=r"(r[2]), "=r"(r[3]) : "r"(addr));
}
__device__ __forceinline__ void mma16816(float* d, const uint32_t* a, uint32_t b0, uint32_t b1) {
    asm volatile(
        "mma.sync.aligned.m16n8k16.row.col.f32.bf16.bf16.f32 "
        "{%0,%1,%2,%3}, {%4,%5,%6,%7}, {%8,%9}, {%0,%1,%2,%3};"
        : "+f"(d[0]), "+f"(d[1]), "+f"(d[2]), "+f"(d[3])
        : "r"(a[0]), "r"(a[1]), "r"(a[2]), "r"(a[3]), "r"(b0), "r"(b1));
}
__device__ __forceinline__ float warp_sum(float v) {
#pragma unroll
    for (int o = 16; o; o >>= 1) v += __shfl_xor_sync(0xffffffffu, v, o);
    return v;
}
__device__ __forceinline__ void cp16(uint32_t dst, const void* src) {
    asm volatile("cp.async.cg.shared.global [%0], [%1], 16;" :: "r"(dst), "l"(src));
}

// smem tiles: 64 rows x 256 bf16 (512B rows), 16B segs XOR-swizzled:
// byte = row*512 + ((seg ^ (row&7)) << 4)
#define SMA_BYTES 32768
#define SM_TOTAL  (2 * SMA_BYTES)
#define NT        512

__global__ void __launch_bounds__(NT, 1) fused_kernel(const float* __restrict__ x,
                                                      float* __restrict__ out) {
    int t = threadIdx.x;
    int wid = t >> 5, lane = t & 31;
    int bid = blockIdx.x;

    extern __shared__ __align__(16) char smem[];
    uint32_t sA = smem_u32(smem);
    uint32_t sB = sA + SMA_BYTES;

    __shared__ float s_sqi[TS], s_sqj[TS];
    __shared__ float rs[16];
    __shared__ bool s_last;

    // ================= phase 1: warp-per-class (128 CTAs x 8 warps) =================
    {
        int c = bid * 8 + wid;   // warps 8..15 and CTAs >= 128 idle here
        if (wid < 8 && c < NCLASS) {
            const float4* base = (const float4*)(x + (size_t)c * KSZ * DIM) + lane * 2;

            float v[KSZ][8];
#pragma unroll
            for (int r = 0; r < KSZ; r++) {
                float4 a = base[r * (DIM / 4)];
                float4 b = base[r * (DIM / 4) + 1];
                v[r][0] = a.x; v[r][1] = a.y; v[r][2] = a.z; v[r][3] = a.w;
                v[r][4] = b.x; v[r][5] = b.y; v[r][6] = b.z; v[r][7] = b.w;
            }
            float ss[KSZ];
#pragma unroll
            for (int r = 0; r < KSZ; r++) {
                float s = 0.0f;
#pragma unroll
                for (int i = 0; i < 8; i++) s = fmaf(v[r][i], v[r][i], s);
                ss[r] = s;
            }
#pragma unroll
            for (int o = 16; o; o >>= 1) {
#pragma unroll
                for (int r = 0; r < KSZ; r++) ss[r] += __shfl_xor_sync(0xffffffffu, ss[r], o);
            }
            float cen[8] = {0, 0, 0, 0, 0, 0, 0, 0};
#pragma unroll
            for (int r = 0; r < KSZ; r++) {
                float inv = rsqrtf(ss[r]);
#pragma unroll
                for (int i = 0; i < 8; i++) {
                    v[r][i] *= inv;
                    cen[i] += v[r][i];
                }
            }
#pragma unroll
            for (int i = 0; i < 8; i++) cen[i] *= (1.0f / KSZ);

            uint32_t pk[4];
#pragma unroll
            for (int i = 0; i < 4; i++) {
                __nv_bfloat162 p = __float22bfloat162_rn(make_float2(cen[2 * i], cen[2 * i + 1]));
                pk[i] = *(uint32_t*)&p;
            }
            *(uint4*)(g_cbf + (size_t)c * DIM + lane * 8) = make_uint4(pk[0], pk[1], pk[2], pk[3]);

            float c2 = 0.0f;
#pragma unroll
            for (int i = 0; i < 8; i++) c2 = fmaf(cen[i], cen[i], c2);
            c2 = warp_sum(c2);
            if (lane == 0) g_sq[c] = c2;
            float cinv = rsqrtf(c2);

            float ds[KSZ];
#pragma unroll
            for (int r = 0; r < KSZ; r++) {
                float s = 0.0f;
#pragma unroll
                for (int i = 0; i < 8; i++) {
                    float diff = v[r][i] - cen[i] * cinv;
                    s = fmaf(diff, diff, s);
                }
                ds[r] = s;
            }
#pragma unroll
            for (int o = 16; o; o >>= 1) {
#pragma unroll
                for (int r = 0; r < KSZ; r++) ds[r] += __shfl_xor_sync(0xffffffffu, ds[r], o);
            }
            float pcsum = 0.0f;
#pragma unroll
            for (int r = 0; r < KSZ; r++) pcsum += sqrtf(ds[r]);
            if (lane == 0) g_pc[c] = pcsum;

            // signal class completion to its block counter
            __syncwarp();
            if (lane == 0) {
                __threadfence();
                atomicAdd(&g_rdy[c >> 6], 1u);
            }
        }
    }

    // ================= dependency wait: only blocks bi, bj =================
    int bi = 0, off = 0;
    while (bid >= off + (TTILE - bi)) { off += TTILE - bi; bi++; }
    int bj = bi + (bid - off);

    if (t == 0) {
        volatile unsigned* ri = &g_rdy[bi];
        volatile unsigned* rj = &g_rdy[bj];
        while (*ri < 64u) __nanosleep(64);
        while (*rj < 64u) __nanosleep(64);
        __threadfence();   // acquire: order subsequent reads of g_cbf / g_sq
    }
    __syncthreads();

    // ================= phase 2: 64x64 pair tile, 16 warps =================
    {
        const char* gA = (const char*)(g_cbf + (size_t)bi * TS * DIM);
        const char* gB = (const char*)(g_cbf + (size_t)bj * TS * DIM);
#pragma unroll
        for (int it = 0; it < 4; it++) {
            int idx = t + NT * it;           // 0..2047 segs per tile
            int row = idx >> 5;
            int seg = idx & 31;
            uint32_t o = (uint32_t)(row * 512 + ((seg ^ (row & 7)) << 4));
            cp16(sA + o, gA + idx * 16);
            cp16(sB + o, gB + idx * 16);
        }
        asm volatile("cp.async.commit_group;");
    }
    if (t < TS) s_sqi[t] = g_sq[bi * TS + t];
    else if (t < 2 * TS) s_sqj[t - TS] = g_sq[bj * TS + (t - TS)];
    asm volatile("cp.async.wait_group 0;" ::: "memory");
    __syncthreads();

    // warp tile 16x16: 4 warps M x 4 warps N
    int wm = wid >> 2, wn = wid & 3;
    int m0 = wm * 16, n0 = wn * 16;
    int lr = lane & 15, lh = lane >> 4;

    float acc[2][4];
#pragma unroll
    for (int b = 0; b < 2; b++)
#pragma unroll
        for (int e = 0; e < 4; e++) acc[b][e] = 0.0f;

#pragma unroll
    for (int kk = 0; kk < 16; kk++) {
        uint32_t af[4], bf[4];
        int seg = kk * 2 + lh;
        {
            int row = m0 + lr;
            ldm_x4(af, sA + row * 512 + ((seg ^ (row & 7)) << 4));
        }
        {
            int row = n0 + lr;
            ldm_x4(bf, sB + row * 512 + ((seg ^ (row & 7)) << 4));
        }
        mma16816(acc[0], af, bf[0], bf[2]);
        mma16816(acc[1], af, bf[1], bf[3]);
    }

    // epilogue: hinge over fragments
    int g = lane >> 2, tg = lane & 3;
    bool diag = (bi == bj);
    float local = 0.0f;
#pragma unroll
    for (int nn = 0; nn < 2; nn++) {
        int r0 = m0 + g;
        int c0 = n0 + nn * 8 + tg * 2;
#pragma unroll
        for (int e = 0; e < 4; e++) {
            int r = r0 + (e >> 1) * 8;
            int c = c0 + (e & 1);
            float dot = acc[nn][e];
            float d2 = s_sqi[r] + s_sqj[c] - 2.0f * dot;
            float d = sqrtf(fmaxf(d2, 1e-12f));
            float h = fmaxf(0.7f - d, 0.0f);
            if (!diag || c > r) local += h;
        }
    }
    local = warp_sum(local);
    if (lane == 0) rs[wid] = local;
    __syncthreads();
    if (t == 0) {
        float s = 0.0f;
#pragma unroll
        for (int w2 = 0; w2 < 16; w2++) s += rs[w2];
        g_ph[bid] = s;
    }

    // ================= phase 3: last block finalizes =================
    __threadfence();
    __syncthreads();
    if (t == 0) s_last = (atomicAdd(&g_cnt, 1u) == (unsigned)(NPAIR - 1));
    __syncthreads();
    if (!s_last) return;

    float s1 = 0.0f, s2 = 0.0f;
#pragma unroll
    for (int i = t; i < NCLASS; i += NT) s1 += g_pc[i];
    if (t < NPAIR) s2 += g_ph[t];
    s1 = warp_sum(s1);
    s2 = warp_sum(s2);
    __shared__ float r1[16], r2[16];
    if (lane == 0) { r1[wid] = s1; r2[wid] = s2; }
    __syncthreads();
    if (t < NBLK) g_rdy[t] = 0;      // reset block counters for next replay
    if (t == 0) {
        float a = 0.0f, b = 0.0f;
#pragma unroll
        for (int w2 = 0; w2 < 16; w2++) { a += r1[w2]; b += r2[w2]; }
        float pc = a * (1.0f / (float)NSAMP);
        float an = b * (2.0f * (float)KSZ / ((float)(NSAMP - KSZ) * (float)NCLASS));
        out[0] = pc + an;
        out[1] = pc;
        out[2] = an;
        g_cnt = 0;                   // reset for next graph replay
    }
}

extern "C" void kernel_launch(void* const* d_in, const int* in_sizes, int n_in,
                              void* d_out, int out_size) {
    const float* x = (const float*)d_in[0];
    float* out = (float*)d_out;

    static bool attr_set = false;
    if (!attr_set) {
        cudaFuncSetAttribute(fused_kernel, cudaFuncAttributeMaxDynamicSharedMemorySize, SM_TOTAL);
        attr_set = true;
    }

    fused_kernel<<<NPAIR, NT, SM_TOTAL>>>(x, out);
}

// round 10
// speedup vs baseline: 1.1622x; 1.1622x over previous
#include <cuda_runtime.h>
#include <cuda_bf16.h>
#include <cstdint>

#define NCLASS 1024
#define DIM    256
#define KSZ    8
#define NSAMP  8192
#define TTILE  16         // 16x16 tiles of 64
#define TS     64         // tile size
#define NPAIR  136        // upper-triangle tile count

// ---------------- scratch (no allocations allowed) ----------------
__device__ __align__(16) __nv_bfloat16 g_cbf[NCLASS * DIM];
__device__ float g_sq[NCLASS];
__device__ float g_pc2[NCLASS * 2];  // per-half-class dist_pc partials
__device__ float g_ph[NPAIR];        // per-tile hinge partials

__device__ __forceinline__ uint32_t smem_u32(const void* p) {
    uint32_t a;
    asm("{ .reg .u64 t; cvta.to.shared.u64 t, %1; cvt.u32.u64 %0, t; }" : "=r"(a) : "l"(p));
    return a;
}
__device__ __forceinline__ void ldm_x4(uint32_t* r, uint32_t addr) {
    asm volatile("ldmatrix.sync.aligned.m8n8.x4.shared.b16 {%0,%1,%2,%3}, [%4];"
                 : "=r"(r[0]), "=r"(r[1]), "=r"(r[2]), "=r"(r[3]) : "r"(addr));
}
__device__ __forceinline__ void mma16816(float* d, const uint32_t* a, uint32_t b0, uint32_t b1) {
    asm volatile(
        "mma.sync.aligned.m16n8k16.row.col.f32.bf16.bf16.f32 "
        "{%0,%1,%2,%3}, {%4,%5,%6,%7}, {%8,%9}, {%0,%1,%2,%3};"
        : "+f"(d[0]), "+f"(d[1]), "+f"(d[2]), "+f"(d[3])
        : "r"(a[0]), "r"(a[1]), "r"(a[2]), "r"(a[3]), "r"(b0), "r"(b1));
}
__device__ __forceinline__ float warp_sum(float v) {
#pragma unroll
    for (int o = 16; o; o >>= 1) v += __shfl_xor_sync(0xffffffffu, v, o);
    return v;
}

// ---------------- kernel 1: half-class-per-warp (256 CTAs x 8 warps) ----------------
// Warp pair (2w, 2w+1) shares class; each warp handles 4 rows. Lane owns dims [8*lane, 8*lane+8).
__global__ void __launch_bounds__(256) class_kernel(const float* __restrict__ x) {
    int t = threadIdx.x;
    int wid = t >> 5, lane = t & 31;
    int c = blockIdx.x * 4 + (wid >> 1);   // 4 classes per CTA
    int h = wid & 1;                        // half index: rows h*4 .. h*4+3

    __shared__ float s_cen[8][256];         // per-warp partial centers, dim d at [w][(d&7)*32 + (d>>3)]

    const float4* base = (const float4*)(x + ((size_t)c * KSZ + h * 4) * DIM) + lane * 2;

    // batch all 8 LDG.128 (4 rows x 2)
    float v[4][8];
#pragma unroll
    for (int r = 0; r < 4; r++) {
        float4 a = base[r * (DIM / 4)];
        float4 b = base[r * (DIM / 4) + 1];
        v[r][0] = a.x; v[r][1] = a.y; v[r][2] = a.z; v[r][3] = a.w;
        v[r][4] = b.x; v[r][5] = b.y; v[r][6] = b.z; v[r][7] = b.w;
    }
    // interleaved row-norm reductions
    float ss[4];
#pragma unroll
    for (int r = 0; r < 4; r++) {
        float s = 0.0f;
#pragma unroll
        for (int i = 0; i < 8; i++) s = fmaf(v[r][i], v[r][i], s);
        ss[r] = s;
    }
#pragma unroll
    for (int o = 16; o; o >>= 1) {
#pragma unroll
        for (int r = 0; r < 4; r++) ss[r] += __shfl_xor_sync(0xffffffffu, ss[r], o);
    }
    float part[8] = {0, 0, 0, 0, 0, 0, 0, 0};
#pragma unroll
    for (int r = 0; r < 4; r++) {
        float inv = rsqrtf(ss[r]);
#pragma unroll
        for (int i = 0; i < 8; i++) {
            v[r][i] *= inv;
            part[i] += v[r][i];
        }
    }
    // exchange partial centers between warp pair (conflict-free: bank = lane)
#pragma unroll
    for (int i = 0; i < 8; i++) s_cen[wid][i * 32 + lane] = part[i];
    __syncthreads();
    float cen[8];
#pragma unroll
    for (int i = 0; i < 8; i++)
        cen[i] = (part[i] + s_cen[wid ^ 1][i * 32 + lane]) * (1.0f / KSZ);

    // even warp stores bf16 center + sq
    if (h == 0) {
        uint32_t pk[4];
#pragma unroll
        for (int i = 0; i < 4; i++) {
            __nv_bfloat162 p = __float22bfloat162_rn(make_float2(cen[2 * i], cen[2 * i + 1]));
            pk[i] = *(uint32_t*)&p;
        }
        *(uint4*)(g_cbf + (size_t)c * DIM + lane * 8) = make_uint4(pk[0], pk[1], pk[2], pk[3]);
    }
    float c2 = 0.0f;
#pragma unroll
    for (int i = 0; i < 8; i++) c2 = fmaf(cen[i], cen[i], c2);
    c2 = warp_sum(c2);
    if (h == 0 && lane == 0) g_sq[c] = c2;
    float cinv = rsqrtf(c2);

    // distances for this warp's 4 rows
    float ds[4];
#pragma unroll
    for (int r = 0; r < 4; r++) {
        float s = 0.0f;
#pragma unroll
        for (int i = 0; i < 8; i++) {
            float diff = v[r][i] - cen[i] * cinv;
            s = fmaf(diff, diff, s);
        }
        ds[r] = s;
    }
#pragma unroll
    for (int o = 16; o; o >>= 1) {
#pragma unroll
        for (int r = 0; r < 4; r++) ds[r] += __shfl_xor_sync(0xffffffffu, ds[r], o);
    }
    float pcsum = sqrtf(ds[0]) + sqrtf(ds[1]) + sqrtf(ds[2]) + sqrtf(ds[3]);
    if (lane == 0) g_pc2[c * 2 + h] = pcsum;
}

// ---------------- kernel 2: bf16 MMA 64x64 pair tiles (no atomics) ----------------
// smem tiles: 64 rows x 256 bf16 (512B rows), 16B segs XOR-swizzled:
// byte = row*512 + ((seg ^ (row&7)) << 4)
#define SMA_BYTES 32768
#define SM_TOTAL  (2 * SMA_BYTES)

__global__ void __launch_bounds__(256, 1) pair_kernel() {
    int t = threadIdx.x;
    int wid = t >> 5, lane = t & 31;

    // triangular bid -> (bi, bj), bj >= bi
    int bid = blockIdx.x;
    int bi = 0, off = 0;
    while (bid >= off + (TTILE - bi)) { off += TTILE - bi; bi++; }
    int bj = bi + (bid - off);

    extern __shared__ __align__(16) char smem[];
    uint32_t sA = smem_u32(smem);
    uint32_t sB = sA + SMA_BYTES;

    __shared__ float s_sqi[TS], s_sqj[TS];
    __shared__ float rs[8];

    {
        const uint4* gA = (const uint4*)(g_cbf + (size_t)bi * TS * DIM);
        const uint4* gB = (const uint4*)(g_cbf + (size_t)bj * TS * DIM);
#pragma unroll
        for (int it = 0; it < 8; it++) {
            int idx = t + 256 * it;          // 0..2047 segs per tile
            int row = idx >> 5;
            int seg = idx & 31;
            uint32_t o = (uint32_t)(row * 512 + ((seg ^ (row & 7)) << 4));
            *(uint4*)(smem + o) = gA[idx];
            *(uint4*)(smem + SMA_BYTES + o) = gB[idx];
        }
    }
    if (t < TS) s_sqi[t] = g_sq[bi * TS + t];
    else if (t < 2 * TS) s_sqj[t - TS] = g_sq[bj * TS + (t - TS)];
    __syncthreads();

    // MMA mainloop: warp tile 32x16 (2 warps M x 4 warps N)
    int wm = wid >> 2, wn = wid & 3;
    int m0 = wm * 32, n0 = wn * 16;
    int lr = lane & 15, lh = lane >> 4;

    float acc[2][2][4];
#pragma unroll
    for (int a = 0; a < 2; a++)
#pragma unroll
        for (int b = 0; b < 2; b++)
#pragma unroll
            for (int e = 0; e < 4; e++) acc[a][b][e] = 0.0f;

#pragma unroll
    for (int kk = 0; kk < 16; kk++) {
        uint32_t af[2][4], bf[4];
        int seg = kk * 2 + lh;
#pragma unroll
        for (int ma = 0; ma < 2; ma++) {
            int row = m0 + ma * 16 + lr;
            ldm_x4(af[ma], sA + row * 512 + ((seg ^ (row & 7)) << 4));
        }
        {
            int row = n0 + lr;
            ldm_x4(bf, sB + row * 512 + ((seg ^ (row & 7)) << 4));
        }
#pragma unroll
        for (int ma = 0; ma < 2; ma++) {
            mma16816(acc[ma][0], af[ma], bf[0], bf[2]);
            mma16816(acc[ma][1], af[ma], bf[1], bf[3]);
        }
    }

    // epilogue: hinge over fragments
    int g = lane >> 2, tg = lane & 3;
    bool diag = (bi == bj);
    float local = 0.0f;
#pragma unroll
    for (int ma = 0; ma < 2; ma++) {
#pragma unroll
        for (int nn = 0; nn < 2; nn++) {
            int r0 = m0 + ma * 16 + g;
            int c0 = n0 + nn * 8 + tg * 2;
#pragma unroll
            for (int e = 0; e < 4; e++) {
                int r = r0 + (e >> 1) * 8;
                int c = c0 + (e & 1);
                float dot = acc[ma][nn][e];
                float d2 = s_sqi[r] + s_sqj[c] - 2.0f * dot;
                float d = sqrtf(fmaxf(d2, 1e-12f));
                float h = fmaxf(0.7f - d, 0.0f);
                if (!diag || c > r) local += h;
            }
        }
    }
    local = warp_sum(local);
    if (lane == 0) rs[wid] = local;
    __syncthreads();
    if (t == 0) {
        float s = 0.0f;
#pragma unroll
        for (int w2 = 0; w2 < 8; w2++) s += rs[w2];
        g_ph[bid] = s;   // plain store — no atomics
    }
}

// ---------------- kernel 3: finalize ----------------
__global__ void __launch_bounds__(256) final_kernel(float* __restrict__ out) {
    int t = threadIdx.x;
    int wid = t >> 5, lane = t & 31;
    float s1 = 0.0f, s2 = 0.0f;
#pragma unroll
    for (int i = t; i < NCLASS * 2; i += 256) s1 += g_pc2[i];
    if (t < NPAIR) s2 += g_ph[t];
    s1 = warp_sum(s1);
    s2 = warp_sum(s2);
    __shared__ float r1[8], r2[8];
    if (lane == 0) { r1[wid] = s1; r2[wid] = s2; }
    __syncthreads();
    if (t == 0) {
        float a = 0.0f, b = 0.0f;
#pragma unroll
        for (int w = 0; w < 8; w++) { a += r1[w]; b += r2[w]; }
        float pc = a * (1.0f / (float)NSAMP);
        float an = b * (2.0f * (float)KSZ / ((float)(NSAMP - KSZ) * (float)NCLASS));
        out[0] = pc + an;
        out[1] = pc;
        out[2] = an;
    }
}

extern "C" void kernel_launch(void* const* d_in, const int* in_sizes, int n_in,
                              void* d_out, int out_size) {
    const float* x = (const float*)d_in[0];
    float* out = (float*)d_out;

    static bool attr_set = false;
    if (!attr_set) {
        cudaFuncSetAttribute(pair_kernel, cudaFuncAttributeMaxDynamicSharedMemorySize, SM_TOTAL);
        attr_set = true;
    }

    class_kernel<<<NCLASS / 4, 256>>>(x);
    pair_kernel<<<NPAIR, 256, SM_TOTAL>>>();
    final_kernel<<<1, 256>>>(out);
}